// round 9
// baseline (speedup 1.0000x reference)
#include <cuda_runtime.h>

// BaseGraphPooling: segment-mean over sorted node_batch.
// node_h: [N,128] fp32, node_batch: [N] int32 sorted, out: [G,128] fp32.
//
// SINGLE kernel, NO grid barrier, per-graph finisher protocol:
//  - 1184 CTAs, fixed contiguous row chunks (perfect per-SM byte balance).
//  - CTA stages its index slice to smem; sub-segment bounds via smem bsearch.
//  - Contributors: red.add scratch + count, fence, then red.add g_ctrb[g].
//  - The unique CTA observing a segment's END is its finisher: after all its
//    own streaming, it computes the exact contributor count (<=3 L2 peeks at
//    chunk-edge elements), spins until g_ctrb[g] matches, divides, writes
//    out[g], zero-fills any empty successor graphs, and re-zeros that graph's
//    scratch/counters (graph-replay safe). Epilogue fully overlaps streaming.

#define NUM_CTAS 1184       // 148 SMs * 8 CTAs/SM
#define MAX_G    1024
#define MAX_RPC  1728       // max rows_per_cta supported by smem staging
#define MAX_REC  64         // finisher records per CTA (data has <= 3)

__device__ float4 g_scratch[MAX_G * 32];  // zero-init at load; finisher re-zeros
__device__ int    g_count[MAX_G];         // rows per graph (atomic)
__device__ int    g_ctrb[MAX_G];          // contributor arrivals per graph

__device__ __forceinline__ float4 f4add(float4 a, float4 b) {
    a.x += b.x; a.y += b.y; a.z += b.z; a.w += b.w; return a;
}

__device__ __forceinline__ void red_add_v4(float4* addr, float4 v) {
    asm volatile("red.global.add.v4.f32 [%0], {%1, %2, %3, %4};"
                 :: "l"(addr), "f"(v.x), "f"(v.y), "f"(v.z), "f"(v.w)
                 : "memory");
}

__device__ __forceinline__ void red_add_s32(int* addr, int v) {
    asm volatile("red.global.add.s32 [%0], %1;" :: "l"(addr), "r"(v) : "memory");
}

__global__ __launch_bounds__(256, 8)
void fused_segment_mean_kernel(const float4* __restrict__ h,    // N*32 float4
                               const int* __restrict__ batch,   // N int32, sorted
                               float4* __restrict__ out,        // G*32 float4
                               int N, int G, int rpc) {
    const int tid = threadIdx.x;
    const int c   = tid & 31;   // float4 column (0..31)
    const int r   = tid >> 5;   // row phase (0..7)
    const int bid = blockIdx.x;

    __shared__ float4 smem[256];
    __shared__ int    sb[MAX_RPC];
    __shared__ int    rec_g[MAX_REC], rec_first[MAX_REC], rec_next[MAX_REC];
    __shared__ int    n_rec_s, cnt_s;

    if (tid == 0) n_rec_s = 0;

    const int c0 = bid * rpc;
    const int c1 = min(c0 + rpc, N);

    if (c0 < c1) {
        const int len = c1 - c0;
        // Stage this CTA's index slice into smem (coalesced burst).
        for (int i = tid; i < len; i += 256)
            sb[i] = batch[c0 + i];
        __syncthreads();

        // bid 0 also zero-fills any empty prefix graphs [0, batch[0]).
        if (bid == 0) {
            const int first_id = sb[0];
            for (int z = tid; z < first_id * 32; z += 256)
                out[z] = make_float4(0.f, 0.f, 0.f, 0.f);
        }

        // First id of the next chunk (G sentinel past the end) — uniform load.
        const int next_id = (c1 < N) ? batch[c1] : G;

        int s = c0;
        while (s < c1) {
            const int g = sb[s - c0];           // current segment id (uniform)
            int lo = s, hi = c1;                // upper_bound via smem bsearch
            while (lo < hi) {
                int mid = (lo + hi) >> 1;
                if (sb[mid - c0] <= g) lo = mid + 1; else hi = mid;
            }
            const int e = lo;

            float4 a0 = make_float4(0.f, 0.f, 0.f, 0.f);
            float4 a1 = a0, a2 = a0, a3 = a0;

            int i = s + r;
            for (; i + 24 < e; i += 32) {
                float4 v0 = __ldcs(&h[(size_t)(i     ) * 32 + c]);
                float4 v1 = __ldcs(&h[(size_t)(i +  8) * 32 + c]);
                float4 v2 = __ldcs(&h[(size_t)(i + 16) * 32 + c]);
                float4 v3 = __ldcs(&h[(size_t)(i + 24) * 32 + c]);
                a0 = f4add(a0, v0);
                a1 = f4add(a1, v1);
                a2 = f4add(a2, v2);
                a3 = f4add(a3, v3);
            }
            for (; i < e; i += 8)
                a0 = f4add(a0, __ldcs(&h[(size_t)i * 32 + c]));

            smem[tid] = f4add(f4add(a0, a1), f4add(a2, a3));
            __syncthreads();

            if (r == 0) {
                float4 acc = smem[c];
                #pragma unroll
                for (int p = 1; p < 8; p++)
                    acc = f4add(acc, smem[p * 32 + c]);
                red_add_v4(&g_scratch[(size_t)g * 32 + c], acc);
                if (c == 0) red_add_s32(&g_count[g], e - s);
                __threadfence();          // each lane orders its own red.adds
                __syncwarp();
                if (c == 0) red_add_s32(&g_ctrb[g], 1);   // arrival signal
            }
            // Record finisher duty: this CTA sees the END of segment g.
            const bool is_end = (e < c1) || (next_id != g);
            if (tid == 0 && is_end) {
                int k = n_rec_s;
                if (k < MAX_REC) {
                    rec_g[k]     = g;
                    rec_first[k] = (s == c0) ? 1 : 0;   // may extend back
                    rec_next[k]  = (e < c1) ? sb[e - c0] : next_id;
                    n_rec_s = k + 1;
                }
            }
            __syncthreads();              // smem reuse + record visibility
            s = e;
        }
    }
    __syncthreads();

    // ---- Pass 2: finisher duties (overlaps other CTAs' streaming) ----
    const int n_rec = n_rec_s;
    for (int k = 0; k < n_rec; k++) {
        const int g = rec_g[k];
        if (tid == 0) {
            // Exact contributor count: walk back over chunks whose last
            // element is g (segments span few chunks; loop is tiny).
            int nc = 1;
            if (rec_first[k] && bid > 0) {
                int kk = bid - 1;
                while (kk >= 0 && batch[(size_t)(kk + 1) * rpc - 1] == g) {
                    nc++;
                    if (batch[(size_t)kk * rpc] != g) break;
                    kk--;
                }
            }
            while (atomicAdd(&g_ctrb[g], 0) < nc)
                __nanosleep(32);
            __threadfence();
            cnt_s = __ldcg(&g_count[g]);
        }
        __syncthreads();

        const int   cnt = cnt_s;
        const float inv = 1.0f / (float)max(cnt, 1);

        if (tid < 32) {
            float4 v = __ldcg(&g_scratch[(size_t)g * 32 + tid]);
            g_scratch[(size_t)g * 32 + tid] = make_float4(0.f, 0.f, 0.f, 0.f);
            v.x *= inv; v.y *= inv; v.z *= inv; v.w *= inv;
            out[(size_t)g * 32 + tid] = v;
        } else if (tid == 32) {
            g_count[g] = 0;
            g_ctrb[g]  = 0;
        }

        // Zero-fill empty successor graphs (g, rec_next) exclusive —
        // contiguous region in out.
        const int gn = rec_next[k];
        const int nz = (gn - g - 1) * 32;
        for (int z = tid; z < nz; z += 256)
            out[(size_t)(g + 1) * 32 + z] = make_float4(0.f, 0.f, 0.f, 0.f);

        __syncthreads();
    }
}

extern "C" void kernel_launch(void* const* d_in, const int* in_sizes, int n_in,
                              void* d_out, int out_size) {
    const float4* h     = (const float4*)d_in[0];
    const int*    batch = (const int*)d_in[1];
    const int N = in_sizes[1];       // number of nodes
    const int G = out_size / 128;    // number of graphs

    int rpc = (N + NUM_CTAS - 1) / NUM_CTAS;   // <= MAX_RPC for this shape
    fused_segment_mean_kernel<<<NUM_CTAS, 256>>>(h, batch, (float4*)d_out,
                                                 N, G, rpc);
}